// round 2
// baseline (speedup 1.0000x reference)
#include <cuda_runtime.h>
#include <math.h>

#define HID 256
#define NLAYERS 15
#define MAXN 50000
#define MAXE 500000
#define EPS 1e-5f

// ---------------- scratch (static device globals; no runtime allocation) ---
__device__ float g_h[(size_t)MAXN * HID];     // node features (carry)
__device__ float g_agg[(size_t)MAXN * HID];   // neighbor aggregation
__device__ float g_out[(size_t)MAXN * HID];   // pre-BN layer output
__device__ float g_z1[(size_t)MAXE * HID];    // edge MLP hidden 1
__device__ float g_z2[(size_t)MAXE * HID];    // edge MLP hidden 2
__device__ float g_sum[HID];
__device__ float g_sq[HID];
__device__ float g_scale[HID];
__device__ float g_shift[HID];

// ---------------- input fc: h = x @ W_in^T  (IN_CH = 2) --------------------
__global__ void k_input(const float* __restrict__ x,
                        const float* __restrict__ Win, int N) {
    int i = blockIdx.x;
    int j = threadIdx.x;
    if (i < N)
        g_h[(size_t)i * HID + j] =
            fmaf(x[2 * i], Win[2 * j], x[2 * i + 1] * Win[2 * j + 1]);
}

__global__ void k_zero_agg(int n) {
    int i = blockIdx.x * blockDim.x + threadIdx.x;
    if (i < n) g_agg[i] = 0.f;
}

// ---------------- scatter-add: agg[dst] += h[src] --------------------------
__global__ void k_scatter(const int* __restrict__ ei, int E) {
    int e = blockIdx.x;
    int f = threadIdx.x;
    int s = ei[e];
    int d = ei[E + e];
    atomicAdd(&g_agg[(size_t)d * HID + f], g_h[(size_t)s * HID + f]);
}

// ---------------- fp32 register-tiled GEMM: C = A @ W^T (+bias)(+C)(relu) --
#define BM 64
#define BN 64
#define BK 16

// mode: 0 -> A=g_agg, C=g_out ; 1 -> A=g_h, C=g_out ; 2 -> A=g_z1, C=g_z2
__global__ void __launch_bounds__(256)
k_gemm(int mode, const float* __restrict__ W, const float* __restrict__ bias,
       int M, int K, int accum, int relu) {
    const float* A = (mode == 0) ? g_agg : (mode == 1) ? g_h : g_z1;
    float* C = (mode == 2) ? g_z2 : g_out;

    __shared__ float As[BK][BM];
    __shared__ float Ws[BK][BN];

    int bm = blockIdx.y * BM, bn = blockIdx.x * BN;
    int tid = threadIdx.x;
    int tx = tid & 15, ty = tid >> 4;
    int lr = tid >> 2, lk = (tid & 3) * 4;

    float acc[4][4] = {};

    for (int k0 = 0; k0 < K; k0 += BK) {
        float4 v = make_float4(0.f, 0.f, 0.f, 0.f);
        int gr = bm + lr;
        if (gr < M)
            v = *reinterpret_cast<const float4*>(A + (size_t)gr * K + k0 + lk);
        As[lk + 0][lr] = v.x; As[lk + 1][lr] = v.y;
        As[lk + 2][lr] = v.z; As[lk + 3][lr] = v.w;

        float4 w = *reinterpret_cast<const float4*>(
            W + (size_t)(bn + lr) * K + k0 + lk);
        Ws[lk + 0][lr] = w.x; Ws[lk + 1][lr] = w.y;
        Ws[lk + 2][lr] = w.z; Ws[lk + 3][lr] = w.w;
        __syncthreads();

#pragma unroll
        for (int kk = 0; kk < BK; kk++) {
            float a[4], b[4];
#pragma unroll
            for (int i = 0; i < 4; i++) a[i] = As[kk][ty * 4 + i];
#pragma unroll
            for (int j = 0; j < 4; j++) b[j] = Ws[kk][tx * 4 + j];
#pragma unroll
            for (int i = 0; i < 4; i++)
#pragma unroll
                for (int j = 0; j < 4; j++)
                    acc[i][j] = fmaf(a[i], b[j], acc[i][j]);
        }
        __syncthreads();
    }

#pragma unroll
    for (int i = 0; i < 4; i++) {
        int r = bm + ty * 4 + i;
        if (r >= M) continue;
#pragma unroll
        for (int j = 0; j < 4; j++) {
            int c = bn + tx * 4 + j;
            float vv = acc[i][j];
            if (bias) vv += bias[c];
            if (accum) vv += C[(size_t)r * HID + c];
            if (relu) vv = fmaxf(vv, 0.f);
            C[(size_t)r * HID + c] = vv;
        }
    }
}

// ---------------- edge gather-GEMM: z1 = relu(cat(h[src],h[dst]) @ W1^T + b1)
__global__ void __launch_bounds__(256)
k_gemm_gather(const int* __restrict__ ei, int E, const float* __restrict__ W,
              const float* __restrict__ bias) {
    __shared__ float As[BK][BM];
    __shared__ float Ws[BK][BN];
    __shared__ int s_src[BM], s_dst[BM];

    int bm = blockIdx.y * BM, bn = blockIdx.x * BN;
    int tid = threadIdx.x;
    int tx = tid & 15, ty = tid >> 4;
    int lr = tid >> 2, lk = (tid & 3) * 4;

    if (tid < BM) {
        int e = bm + tid;
        s_src[tid] = (e < E) ? ei[e] : 0;
        s_dst[tid] = (e < E) ? ei[E + e] : 0;
    }
    __syncthreads();

    float acc[4][4] = {};

    for (int k0 = 0; k0 < 2 * HID; k0 += BK) {
        int gr = bm + lr;
        float4 v = make_float4(0.f, 0.f, 0.f, 0.f);
        int kg = k0 + lk;
        if (gr < E) {
            int node = (kg < HID) ? s_src[lr] : s_dst[lr];
            v = *reinterpret_cast<const float4*>(
                g_h + (size_t)node * HID + (kg & (HID - 1)));
        }
        As[lk + 0][lr] = v.x; As[lk + 1][lr] = v.y;
        As[lk + 2][lr] = v.z; As[lk + 3][lr] = v.w;

        float4 w = *reinterpret_cast<const float4*>(
            W + (size_t)(bn + lr) * (2 * HID) + kg);
        Ws[lk + 0][lr] = w.x; Ws[lk + 1][lr] = w.y;
        Ws[lk + 2][lr] = w.z; Ws[lk + 3][lr] = w.w;
        __syncthreads();

#pragma unroll
        for (int kk = 0; kk < BK; kk++) {
            float a[4], b[4];
#pragma unroll
            for (int i = 0; i < 4; i++) a[i] = As[kk][ty * 4 + i];
#pragma unroll
            for (int j = 0; j < 4; j++) b[j] = Ws[kk][tx * 4 + j];
#pragma unroll
            for (int i = 0; i < 4; i++)
#pragma unroll
                for (int j = 0; j < 4; j++)
                    acc[i][j] = fmaf(a[i], b[j], acc[i][j]);
        }
        __syncthreads();
    }

#pragma unroll
    for (int i = 0; i < 4; i++) {
        int r = bm + ty * 4 + i;
        if (r >= E) continue;
#pragma unroll
        for (int j = 0; j < 4; j++) {
            int c = bn + tx * 4 + j;
            float vv = fmaxf(acc[i][j] + bias[c], 0.f);
            g_z1[(size_t)r * HID + c] = vv;
        }
    }
}

// ---------------- batchnorm (training-mode batch stats) --------------------
__global__ void k_bn_zero() {
    int c = threadIdx.x;
    g_sum[c] = 0.f;
    g_sq[c] = 0.f;
}

__global__ void k_bn_partial(int N) {
    int c = threadIdx.x;
    int r0 = blockIdx.x * 256;
    int r1 = min(r0 + 256, N);
    float s = 0.f, q = 0.f;
    for (int r = r0; r < r1; r++) {
        float v = g_out[(size_t)r * HID + c];
        s += v;
        q = fmaf(v, v, q);
    }
    atomicAdd(&g_sum[c], s);
    atomicAdd(&g_sq[c], q);
}

__global__ void k_bn_final(const float* __restrict__ gamma,
                           const float* __restrict__ beta, float invN) {
    int c = threadIdx.x;
    float m = g_sum[c] * invN;
    float var = g_sq[c] * invN - m * m;
    float rstd = rsqrtf(var + EPS);
    float sc = rstd * gamma[c];
    g_scale[c] = sc;
    g_shift[c] = beta[c] - m * sc;
}

__global__ void k_bn_apply(int N) {
    int i = blockIdx.x, c = threadIdx.x;
    size_t idx = (size_t)i * HID + c;
    float v = fmaf(g_out[idx], g_scale[c], g_shift[c]);
    g_h[idx] += fmaxf(v, 0.f);
}

// ---------------- final: sigmoid(z2 @ W3^T + b3), one warp per edge --------
__global__ void k_final(const float* __restrict__ W3,
                        const float* __restrict__ b3,
                        float* __restrict__ out, int E) {
    int w = threadIdx.x >> 5, lane = threadIdx.x & 31;
    int e = blockIdx.x * 8 + w;
    if (e >= E) return;
    const float* z = g_z2 + (size_t)e * HID;
    float s = 0.f;
#pragma unroll
    for (int i = 0; i < 8; i++)
        s = fmaf(z[lane + 32 * i], W3[lane + 32 * i], s);
#pragma unroll
    for (int o = 16; o; o >>= 1) s += __shfl_xor_sync(0xffffffffu, s, o);
    if (lane == 0) out[e] = 1.f / (1.f + expf(-(s + b3[0])));
}

// ---------------- host orchestration ---------------------------------------
extern "C" void kernel_launch(void* const* d_in, const int* in_sizes, int n_in,
                              void* d_out, int out_size) {
    const float* x     = (const float*)d_in[0];
    const int*   ei    = (const int*)d_in[1];
    const float* Win   = (const float*)d_in[2];
    const float* Wrel  = (const float*)d_in[3];
    const float* brel  = (const float*)d_in[4];
    const float* Wroot = (const float*)d_in[5];
    const float* gamma = (const float*)d_in[6];
    const float* beta  = (const float*)d_in[7];
    const float* W1    = (const float*)d_in[8];
    const float* b1    = (const float*)d_in[9];
    const float* W2    = (const float*)d_in[10];
    const float* b2    = (const float*)d_in[11];
    const float* W3    = (const float*)d_in[12];
    const float* b3    = (const float*)d_in[13];

    int N = in_sizes[0] / 2;
    int E = in_sizes[1] / 2;
    float* out = (float*)d_out;

    k_input<<<N, HID>>>(x, Win, N);

    dim3 gN(HID / BN, (N + BM - 1) / BM);
    dim3 gE(HID / BN, (E + BM - 1) / BM);
    int nh = N * HID;

    for (int l = 0; l < NLAYERS; l++) {
        k_zero_agg<<<(nh + 255) / 256, 256>>>(nh);
        k_scatter<<<E, HID>>>(ei, E);
        // out = agg @ Wrel^T + brel
        k_gemm<<<gN, 256>>>(0, Wrel + (size_t)l * HID * HID,
                            brel + (size_t)l * HID, N, HID, 0, 0);
        // out += h @ Wroot^T
        k_gemm<<<gN, 256>>>(1, Wroot + (size_t)l * HID * HID, nullptr,
                            N, HID, 1, 0);
        // batchnorm + relu + residual
        k_bn_zero<<<1, HID>>>();
        k_bn_partial<<<(N + 255) / 256, HID>>>(N);
        k_bn_final<<<1, HID>>>(gamma + (size_t)l * HID,
                               beta + (size_t)l * HID, 1.0f / (float)N);
        k_bn_apply<<<N, HID>>>(N);
    }

    // edge MLP
    k_gemm_gather<<<gE, 256>>>(ei, E, W1, b1);
    k_gemm<<<gE, 256>>>(2, W2, b2, E, HID, 0, 1);
    k_final<<<(E + 7) / 8, 256>>>(W3, b3, out, E);
}